// round 1
// baseline (speedup 1.0000x reference)
#include <cuda_runtime.h>
#include <math.h>

#define BSZ 2
#define SEQ 2048
#define EMB 768
#define NH  12
#define HD  64
#define BH  (BSZ*NH)     /* 24  */
#define MTOK (BSZ*SEQ)   /* 4096 */

// ---------------------------------------------------------------------------
// Scratch (no cudaMalloc allowed): Q/K/V in [bh][s][d] layout, attn out in
// [token][e] layout, plus a mask-nonzero flag.
// ---------------------------------------------------------------------------
__device__ float g_Q[BH * SEQ * HD];
__device__ float g_K[BH * SEQ * HD];
__device__ float g_V[BH * SEQ * HD];
__device__ float g_O[MTOK * EMB];
__device__ int   g_mask_nz;

// ---------------------------------------------------------------------------
// Reset + scan: detect whether attention_mask has any nonzero element.
// If all-zero (it is, for this problem's inputs) the attention kernel skips
// 400MB of mask reads. Fully general: falls back to reading mask otherwise.
// ---------------------------------------------------------------------------
__global__ void reset_flag_kernel() { g_mask_nz = 0; }

__global__ void scan_mask_kernel(const float* __restrict__ mask, int n4) {
    int i = blockIdx.x * blockDim.x + threadIdx.x;
    int stride = gridDim.x * blockDim.x;
    int nz = 0;
    for (; i < n4; i += stride) {
        float4 v = ((const float4*)mask)[i];
        nz |= (v.x != 0.f) | (v.y != 0.f) | (v.z != 0.f) | (v.w != 0.f);
    }
    if (__syncthreads_or(nz)) {
        if (threadIdx.x == 0) atomicOr(&g_mask_nz, 1);
    }
}

// ---------------------------------------------------------------------------
// Fused QKV projection:  out = (X @ W^T + b) [* 0.125 for Q]
// NT GEMM, BM=BN=128, BK=16, 256 threads, 8x8 per-thread microtile.
// blockIdx.x in [0,18): segment = x/6 (0:Q 1:K 2:V), n-block = x%6.
// Output written directly in [bh][s][d] layout.
// ---------------------------------------------------------------------------
__global__ void __launch_bounds__(256) qkv_gemm_kernel(
    const float* __restrict__ X,
    const float* __restrict__ Wq, const float* __restrict__ bq,
    const float* __restrict__ Wk, const float* __restrict__ bk,
    const float* __restrict__ Wv, const float* __restrict__ bv)
{
    __shared__ float As[16][132];
    __shared__ float Bs[16][132];

    int bx  = blockIdx.x;
    int seg = bx / 6;
    int bn  = (bx % 6) * 128;
    int bm  = blockIdx.y * 128;

    const float* W    = (seg == 0) ? Wq : (seg == 1) ? Wk : Wv;
    const float* bias = (seg == 0) ? bq : (seg == 1) ? bk : bv;
    float*       out  = (seg == 0) ? g_Q : (seg == 1) ? g_K : g_V;
    const float scale = (seg == 0) ? 0.125f : 1.0f;  // HD^-0.5 = 1/8 exact

    int tid = threadIdx.x;
    int lr  = tid >> 2;          // 0..63
    int lc  = (tid & 3) * 4;     // 0,4,8,12
    int tx  = tid & 15, ty = tid >> 4;

    float acc[8][8];
#pragma unroll
    for (int i = 0; i < 8; i++)
#pragma unroll
        for (int j = 0; j < 8; j++) acc[i][j] = 0.f;

    for (int k0 = 0; k0 < EMB; k0 += 16) {
#pragma unroll
        for (int it = 0; it < 2; it++) {
            int r = lr + it * 64;
            float4 va = *(const float4*)(X + (size_t)(bm + r) * EMB + k0 + lc);
            As[lc + 0][r] = va.x; As[lc + 1][r] = va.y;
            As[lc + 2][r] = va.z; As[lc + 3][r] = va.w;
            float4 vb = *(const float4*)(W + (size_t)(bn + r) * EMB + k0 + lc);
            Bs[lc + 0][r] = vb.x; Bs[lc + 1][r] = vb.y;
            Bs[lc + 2][r] = vb.z; Bs[lc + 3][r] = vb.w;
        }
        __syncthreads();
#pragma unroll
        for (int k = 0; k < 16; k++) {
            float a[8], b[8];
            *(float4*)(a)     = *(const float4*)&As[k][ty * 8];
            *(float4*)(a + 4) = *(const float4*)&As[k][ty * 8 + 4];
            *(float4*)(b)     = *(const float4*)&Bs[k][tx * 8];
            *(float4*)(b + 4) = *(const float4*)&Bs[k][tx * 8 + 4];
#pragma unroll
            for (int i = 0; i < 8; i++)
#pragma unroll
                for (int j = 0; j < 8; j++) acc[i][j] += a[i] * b[j];
        }
        __syncthreads();
    }

#pragma unroll
    for (int i = 0; i < 8; i++) {
        int m = bm + ty * 8 + i;
        int b = m / SEQ, s = m % SEQ;
#pragma unroll
        for (int j4 = 0; j4 < 2; j4++) {
            int n = bn + tx * 8 + j4 * 4;
            int h = n >> 6, d = n & 63;          // n..n+3 stay within one head
            float4 v;
            v.x = (acc[i][j4 * 4 + 0] + bias[n + 0]) * scale;
            v.y = (acc[i][j4 * 4 + 1] + bias[n + 1]) * scale;
            v.z = (acc[i][j4 * 4 + 2] + bias[n + 2]) * scale;
            v.w = (acc[i][j4 * 4 + 3] + bias[n + 3]) * scale;
            *(float4*)(out + ((size_t)((b * NH + h) * SEQ + s)) * HD + d) = v;
        }
    }
}

// ---------------------------------------------------------------------------
// Output projection: d_out = g_O @ Wo^T + bo   (plain row-major out)
// ---------------------------------------------------------------------------
__global__ void __launch_bounds__(256) oproj_gemm_kernel(
    const float* __restrict__ W, const float* __restrict__ bias,
    float* __restrict__ C)
{
    __shared__ float As[16][132];
    __shared__ float Bs[16][132];

    int bn = blockIdx.x * 128;
    int bm = blockIdx.y * 128;
    const float* A = g_O;

    int tid = threadIdx.x;
    int lr  = tid >> 2;
    int lc  = (tid & 3) * 4;
    int tx  = tid & 15, ty = tid >> 4;

    float acc[8][8];
#pragma unroll
    for (int i = 0; i < 8; i++)
#pragma unroll
        for (int j = 0; j < 8; j++) acc[i][j] = 0.f;

    for (int k0 = 0; k0 < EMB; k0 += 16) {
#pragma unroll
        for (int it = 0; it < 2; it++) {
            int r = lr + it * 64;
            float4 va = *(const float4*)(A + (size_t)(bm + r) * EMB + k0 + lc);
            As[lc + 0][r] = va.x; As[lc + 1][r] = va.y;
            As[lc + 2][r] = va.z; As[lc + 3][r] = va.w;
            float4 vb = *(const float4*)(W + (size_t)(bn + r) * EMB + k0 + lc);
            Bs[lc + 0][r] = vb.x; Bs[lc + 1][r] = vb.y;
            Bs[lc + 2][r] = vb.z; Bs[lc + 3][r] = vb.w;
        }
        __syncthreads();
#pragma unroll
        for (int k = 0; k < 16; k++) {
            float a[8], b[8];
            *(float4*)(a)     = *(const float4*)&As[k][ty * 8];
            *(float4*)(a + 4) = *(const float4*)&As[k][ty * 8 + 4];
            *(float4*)(b)     = *(const float4*)&Bs[k][tx * 8];
            *(float4*)(b + 4) = *(const float4*)&Bs[k][tx * 8 + 4];
#pragma unroll
            for (int i = 0; i < 8; i++)
#pragma unroll
                for (int j = 0; j < 8; j++) acc[i][j] += a[i] * b[j];
        }
        __syncthreads();
    }

#pragma unroll
    for (int i = 0; i < 8; i++) {
        int m = bm + ty * 8 + i;
#pragma unroll
        for (int j4 = 0; j4 < 2; j4++) {
            int n = bn + tx * 8 + j4 * 4;
            float4 v;
            v.x = acc[i][j4 * 4 + 0] + bias[n + 0];
            v.y = acc[i][j4 * 4 + 1] + bias[n + 1];
            v.z = acc[i][j4 * 4 + 2] + bias[n + 2];
            v.w = acc[i][j4 * 4 + 3] + bias[n + 3];
            *(float4*)(C + (size_t)m * EMB + n) = v;
        }
    }
}

// ---------------------------------------------------------------------------
// Flash attention, fp32. Grid: (SEQ/32 q-tiles, BH). Block: 256 thr (8 warps).
// Each warp owns 4 query rows; each query row is owned by an 8-lane group.
// Within a group, lane `grp` owns k columns {8j+grp} of the 64-key tile and
// d columns {grp*4..grp*4+3, 32+grp*4..+3} of the output. Online softmax with
// width-8 shuffle reductions; P@V via fully unrolled width-8 shuffles
// (no P staging in shared memory).
// ---------------------------------------------------------------------------
__global__ void __launch_bounds__(256) attn_kernel(
    const float* __restrict__ mask,       // [B][S][S]
    const float* __restrict__ attn_bias,  // [BH][S]
    const float* __restrict__ beta_p,
    const float* __restrict__ bbias_p)
{
    __shared__ float Qs[32][68];
    __shared__ float Ks[64][68];
    __shared__ float Vs[64][68];
    __shared__ float biasS[64];

    int qt   = blockIdx.x;
    int bh   = blockIdx.y;
    int b    = bh / NH;
    int h    = bh % NH;
    int q0   = qt * 32;
    int tid  = threadIdx.x;
    int lane = tid & 31;
    int w    = tid >> 5;
    int grp  = lane & 7;
    int qrow = w * 4 + (lane >> 3);    // 0..31
    int q    = q0 + qrow;

    const float beta  = beta_p[0];
    const float bbias = bbias_p[0];
    const int masknz  = g_mask_nz;

    // Load Q tile (32 x 64) into smem
    {
        const float* Qg = g_Q + ((size_t)bh * SEQ + q0) * HD;
        int r = tid >> 3;            // 0..31
        int c = (tid & 7) * 8;       // 0..56
        float4 v0 = *(const float4*)(Qg + (size_t)r * HD + c);
        float4 v1 = *(const float4*)(Qg + (size_t)r * HD + c + 4);
        *(float4*)&Qs[r][c]     = v0;
        *(float4*)&Qs[r][c + 4] = v1;
    }

    float m_run = -1e30f, l_run = 0.f;
    float oacc[8];
#pragma unroll
    for (int i = 0; i < 8; i++) oacc[i] = 0.f;

    const float* Kg    = g_K + (size_t)bh * SEQ * HD;
    const float* Vg    = g_V + (size_t)bh * SEQ * HD;
    const float* biasg = attn_bias + (size_t)bh * SEQ;

    for (int k0 = 0; k0 < SEQ; k0 += 64) {
        __syncthreads();   // prev tile's PV done (also fences Q store, iter 0)
        // Load K,V tiles (64 x 64 each)
        {
            int r = tid >> 2;           // 0..63
            int c = (tid & 3) * 16;     // 0,16,32,48
            const float* kp = Kg + (size_t)(k0 + r) * HD + c;
            const float* vp = Vg + (size_t)(k0 + r) * HD + c;
#pragma unroll
            for (int u = 0; u < 4; u++) {
                *(float4*)&Ks[r][c + u * 4] = *(const float4*)(kp + u * 4);
                *(float4*)&Vs[r][c + u * 4] = *(const float4*)(vp + u * 4);
            }
            if (tid < 64) biasS[tid] = beta * biasg[k0 + tid] + bbias;
        }
        __syncthreads();

        // Scores: s[j] = q . K[8j+grp]
        float s[8];
#pragma unroll
        for (int j = 0; j < 8; j++) s[j] = 0.f;
#pragma unroll
        for (int d4 = 0; d4 < 16; d4++) {
            float4 qv = *(const float4*)&Qs[qrow][d4 * 4];
#pragma unroll
            for (int j = 0; j < 8; j++) {
                float4 kv = *(const float4*)&Ks[8 * j + grp][d4 * 4];
                s[j] += qv.x * kv.x + qv.y * kv.y + qv.z * kv.z + qv.w * kv.w;
            }
        }
        // bias (+mask if any nonzero)
#pragma unroll
        for (int j = 0; j < 8; j++) {
            float t = s[j] + biasS[8 * j + grp];
            if (masknz)
                t += mask[((size_t)b * SEQ + q) * SEQ + k0 + 8 * j + grp];
            s[j] = t;
        }

        // Row max (own 8, then across the 8-lane group)
        float mx = s[0];
#pragma unroll
        for (int j = 1; j < 8; j++) mx = fmaxf(mx, s[j]);
        mx = fmaxf(mx, __shfl_xor_sync(0xffffffffu, mx, 1, 8));
        mx = fmaxf(mx, __shfl_xor_sync(0xffffffffu, mx, 2, 8));
        mx = fmaxf(mx, __shfl_xor_sync(0xffffffffu, mx, 4, 8));

        float m_new = fmaxf(m_run, mx);
        float alpha = __expf(m_run - m_new);

        float p[8];
        float lsum = 0.f;
#pragma unroll
        for (int j = 0; j < 8; j++) {
            p[j] = __expf(s[j] - m_new);
            lsum += p[j];
        }
        lsum += __shfl_xor_sync(0xffffffffu, lsum, 1, 8);
        lsum += __shfl_xor_sync(0xffffffffu, lsum, 2, 8);
        lsum += __shfl_xor_sync(0xffffffffu, lsum, 4, 8);

        l_run = l_run * alpha + lsum;
        m_run = m_new;
#pragma unroll
        for (int i = 0; i < 8; i++) oacc[i] *= alpha;

        // P @ V : broadcast p across the group, accumulate own d-segments
#pragma unroll
        for (int j = 0; j < 8; j++) {
#pragma unroll
            for (int src = 0; src < 8; src++) {
                float pv = __shfl_sync(0xffffffffu, p[j], src, 8);
                int kk = 8 * j + src;
                float4 v0 = *(const float4*)&Vs[kk][grp * 4];
                float4 v1 = *(const float4*)&Vs[kk][32 + grp * 4];
                oacc[0] += pv * v0.x; oacc[1] += pv * v0.y;
                oacc[2] += pv * v0.z; oacc[3] += pv * v0.w;
                oacc[4] += pv * v1.x; oacc[5] += pv * v1.y;
                oacc[6] += pv * v1.z; oacc[7] += pv * v1.w;
            }
        }
    }

    // Normalize + write to g_O[token][h*64 + d]
    float inv = 1.f / l_run;
    float4 o0, o1;
    o0.x = oacc[0] * inv; o0.y = oacc[1] * inv;
    o0.z = oacc[2] * inv; o0.w = oacc[3] * inv;
    o1.x = oacc[4] * inv; o1.y = oacc[5] * inv;
    o1.z = oacc[6] * inv; o1.w = oacc[7] * inv;
    float* Og = g_O + ((size_t)(b * SEQ + q)) * EMB + h * HD;
    *(float4*)(Og + grp * 4)      = o0;
    *(float4*)(Og + 32 + grp * 4) = o1;
}

// ---------------------------------------------------------------------------
// Launch
// ---------------------------------------------------------------------------
extern "C" void kernel_launch(void* const* d_in, const int* in_sizes, int n_in,
                              void* d_out, int out_size) {
    const float* X     = (const float*)d_in[0];
    const float* mask  = (const float*)d_in[1];
    const float* abias = (const float*)d_in[2];
    const float* Wq    = (const float*)d_in[3];
    const float* bq    = (const float*)d_in[4];
    const float* Wk    = (const float*)d_in[5];
    const float* bk    = (const float*)d_in[6];
    const float* Wv    = (const float*)d_in[7];
    const float* bv    = (const float*)d_in[8];
    const float* Wo    = (const float*)d_in[9];
    const float* bo    = (const float*)d_in[10];
    const float* beta  = (const float*)d_in[11];
    const float* bbias = (const float*)d_in[12];
    float* out = (float*)d_out;

    reset_flag_kernel<<<1, 32>>>();
    scan_mask_kernel<<<1024, 256>>>(mask, BSZ * SEQ * SEQ / 4);
    qkv_gemm_kernel<<<dim3(18, 32), 256>>>(X, Wq, bq, Wk, bk, Wv, bv);
    attn_kernel<<<dim3(SEQ / 32, BH), 256>>>(mask, abias, beta, bbias);
    oproj_gemm_kernel<<<dim3(6, 32), 256>>>(Wo, bo, out);
}

// round 2
// speedup vs baseline: 2.4347x; 2.4347x over previous
#include <cuda_runtime.h>
#include <math.h>

#define BSZ 2
#define SEQ 2048
#define EMB 768
#define NH  12
#define HD  64
#define BH  (BSZ*NH)     /* 24  */
#define MTOK (BSZ*SEQ)   /* 4096 */

// ---------------------------------------------------------------------------
// Scratch (no cudaMalloc allowed)
// ---------------------------------------------------------------------------
__device__ float g_Q[BH * SEQ * HD];
__device__ float g_K[BH * SEQ * HD];
__device__ float g_V[BH * SEQ * HD];
__device__ float g_O[MTOK * EMB];
__device__ int   g_mask_nz;

// ---------------------------------------------------------------------------
// Mask scan (mask is all zeros for this problem; detected at runtime)
// ---------------------------------------------------------------------------
__global__ void reset_flag_kernel() { g_mask_nz = 0; }

__global__ void scan_mask_kernel(const float* __restrict__ mask, int n4) {
    int i = blockIdx.x * blockDim.x + threadIdx.x;
    int stride = gridDim.x * blockDim.x;
    int nz = 0;
    for (; i < n4; i += stride) {
        float4 v = ((const float4*)mask)[i];
        nz |= (v.x != 0.f) | (v.y != 0.f) | (v.z != 0.f) | (v.w != 0.f);
    }
    if (__syncthreads_or(nz)) {
        if (threadIdx.x == 0) atomicOr(&g_mask_nz, 1);
    }
}

// ---------------------------------------------------------------------------
// tf32 helpers
// ---------------------------------------------------------------------------
__device__ __forceinline__ unsigned cvt_tf32(float x) {
    unsigned r;
    asm("cvt.rna.tf32.f32 %0, %1;" : "=r"(r) : "f"(x));
    return r;
}

__device__ __forceinline__ void mma_tf32(float c[4], const unsigned a[4],
                                         unsigned b0, unsigned b1) {
    asm("mma.sync.aligned.m16n8k8.row.col.f32.tf32.tf32.f32 "
        "{%0,%1,%2,%3},{%4,%5,%6,%7},{%8,%9},{%0,%1,%2,%3};"
        : "+f"(c[0]), "+f"(c[1]), "+f"(c[2]), "+f"(c[3])
        : "r"(a[0]), "r"(a[1]), "r"(a[2]), "r"(a[3]), "r"(b0), "r"(b1));
}

// ---------------------------------------------------------------------------
// Fused QKV projection (fp32 SIMT; unchanged from R1)
// ---------------------------------------------------------------------------
__global__ void __launch_bounds__(256) qkv_gemm_kernel(
    const float* __restrict__ X,
    const float* __restrict__ Wq, const float* __restrict__ bq,
    const float* __restrict__ Wk, const float* __restrict__ bk,
    const float* __restrict__ Wv, const float* __restrict__ bv)
{
    __shared__ float As[16][132];
    __shared__ float Bs[16][132];

    int bx  = blockIdx.x;
    int seg = bx / 6;
    int bn  = (bx % 6) * 128;
    int bm  = blockIdx.y * 128;

    const float* W    = (seg == 0) ? Wq : (seg == 1) ? Wk : Wv;
    const float* bias = (seg == 0) ? bq : (seg == 1) ? bk : bv;
    float*       out  = (seg == 0) ? g_Q : (seg == 1) ? g_K : g_V;
    const float scale = (seg == 0) ? 0.125f : 1.0f;

    int tid = threadIdx.x;
    int lr  = tid >> 2;
    int lc  = (tid & 3) * 4;
    int tx  = tid & 15, ty = tid >> 4;

    float acc[8][8];
#pragma unroll
    for (int i = 0; i < 8; i++)
#pragma unroll
        for (int j = 0; j < 8; j++) acc[i][j] = 0.f;

    for (int k0 = 0; k0 < EMB; k0 += 16) {
#pragma unroll
        for (int it = 0; it < 2; it++) {
            int r = lr + it * 64;
            float4 va = *(const float4*)(X + (size_t)(bm + r) * EMB + k0 + lc);
            As[lc + 0][r] = va.x; As[lc + 1][r] = va.y;
            As[lc + 2][r] = va.z; As[lc + 3][r] = va.w;
            float4 vb = *(const float4*)(W + (size_t)(bn + r) * EMB + k0 + lc);
            Bs[lc + 0][r] = vb.x; Bs[lc + 1][r] = vb.y;
            Bs[lc + 2][r] = vb.z; Bs[lc + 3][r] = vb.w;
        }
        __syncthreads();
#pragma unroll
        for (int k = 0; k < 16; k++) {
            float a[8], b[8];
            *(float4*)(a)     = *(const float4*)&As[k][ty * 8];
            *(float4*)(a + 4) = *(const float4*)&As[k][ty * 8 + 4];
            *(float4*)(b)     = *(const float4*)&Bs[k][tx * 8];
            *(float4*)(b + 4) = *(const float4*)&Bs[k][tx * 8 + 4];
#pragma unroll
            for (int i = 0; i < 8; i++)
#pragma unroll
                for (int j = 0; j < 8; j++) acc[i][j] += a[i] * b[j];
        }
        __syncthreads();
    }

#pragma unroll
    for (int i = 0; i < 8; i++) {
        int m = bm + ty * 8 + i;
        int b = m / SEQ, s = m % SEQ;
#pragma unroll
        for (int j4 = 0; j4 < 2; j4++) {
            int n = bn + tx * 8 + j4 * 4;
            int h = n >> 6, d = n & 63;
            float4 v;
            v.x = (acc[i][j4 * 4 + 0] + bias[n + 0]) * scale;
            v.y = (acc[i][j4 * 4 + 1] + bias[n + 1]) * scale;
            v.z = (acc[i][j4 * 4 + 2] + bias[n + 2]) * scale;
            v.w = (acc[i][j4 * 4 + 3] + bias[n + 3]) * scale;
            *(float4*)(out + ((size_t)((b * NH + h) * SEQ + s)) * HD + d) = v;
        }
    }
}

// ---------------------------------------------------------------------------
// Output projection (fp32 SIMT; unchanged)
// ---------------------------------------------------------------------------
__global__ void __launch_bounds__(256) oproj_gemm_kernel(
    const float* __restrict__ W, const float* __restrict__ bias,
    float* __restrict__ C)
{
    __shared__ float As[16][132];
    __shared__ float Bs[16][132];

    int bn = blockIdx.x * 128;
    int bm = blockIdx.y * 128;
    const float* A = g_O;

    int tid = threadIdx.x;
    int lr  = tid >> 2;
    int lc  = (tid & 3) * 4;
    int tx  = tid & 15, ty = tid >> 4;

    float acc[8][8];
#pragma unroll
    for (int i = 0; i < 8; i++)
#pragma unroll
        for (int j = 0; j < 8; j++) acc[i][j] = 0.f;

    for (int k0 = 0; k0 < EMB; k0 += 16) {
#pragma unroll
        for (int it = 0; it < 2; it++) {
            int r = lr + it * 64;
            float4 va = *(const float4*)(A + (size_t)(bm + r) * EMB + k0 + lc);
            As[lc + 0][r] = va.x; As[lc + 1][r] = va.y;
            As[lc + 2][r] = va.z; As[lc + 3][r] = va.w;
            float4 vb = *(const float4*)(W + (size_t)(bn + r) * EMB + k0 + lc);
            Bs[lc + 0][r] = vb.x; Bs[lc + 1][r] = vb.y;
            Bs[lc + 2][r] = vb.z; Bs[lc + 3][r] = vb.w;
        }
        __syncthreads();
#pragma unroll
        for (int k = 0; k < 16; k++) {
            float a[8], b[8];
            *(float4*)(a)     = *(const float4*)&As[k][ty * 8];
            *(float4*)(a + 4) = *(const float4*)&As[k][ty * 8 + 4];
            *(float4*)(b)     = *(const float4*)&Bs[k][tx * 8];
            *(float4*)(b + 4) = *(const float4*)&Bs[k][tx * 8 + 4];
#pragma unroll
            for (int i = 0; i < 8; i++)
#pragma unroll
                for (int j = 0; j < 8; j++) acc[i][j] += a[i] * b[j];
        }
        __syncthreads();
    }

#pragma unroll
    for (int i = 0; i < 8; i++) {
        int m = bm + ty * 8 + i;
#pragma unroll
        for (int j4 = 0; j4 < 2; j4++) {
            int n = bn + tx * 8 + j4 * 4;
            float4 v;
            v.x = acc[i][j4 * 4 + 0] + bias[n + 0];
            v.y = acc[i][j4 * 4 + 1] + bias[n + 1];
            v.z = acc[i][j4 * 4 + 2] + bias[n + 2];
            v.w = acc[i][j4 * 4 + 3] + bias[n + 3];
            *(float4*)(C + (size_t)m * EMB + n) = v;
        }
    }
}

// ---------------------------------------------------------------------------
// Tensor-core flash attention (tf32 mma.sync m16n8k8).
// Grid (SEQ/64, BH), 128 threads (4 warps). Warp w owns q rows [w*16, w*16+16).
// Q lives in registers as 8 A-fragments for the whole kernel.
// Per 64-key tile: scores via 64 mma (K B-frags from smem, stride-68 =>
// conflict-free), online softmax on C-fragments (quad shuffles), P converted
// C-layout -> A-layout via 8 width-4 shuffles per key block, PV via 64 mma
// (V B-frags, stride-72 => conflict-free).
// ---------------------------------------------------------------------------
__global__ void __launch_bounds__(128) attn_tc_kernel(
    const float* __restrict__ mask,       // [B][S][S]
    const float* __restrict__ attn_bias,  // [BH][S]
    const float* __restrict__ beta_p,
    const float* __restrict__ bbias_p)
{
    __shared__ float Ks[64][68];
    __shared__ float Vs[64][72];
    __shared__ float biasS[64];

    int qt   = blockIdx.x;
    int bh   = blockIdx.y;
    int b    = bh / NH;
    int h    = bh % NH;
    int q0   = qt * 64;
    int tid  = threadIdx.x;
    int w    = tid >> 5;
    int lane = tid & 31;
    int g    = lane >> 2;   // group id (row within fragment)
    int m    = lane & 3;    // thread-in-group

    const float beta  = beta_p[0];
    const float bbias = bbias_p[0];
    const int masknz  = g_mask_nz;

    // ---- Q fragments: 16 rows x 64 cols per warp, tf32, persistent ----
    unsigned qf[8][4];
    {
        const float* Qg = g_Q + ((size_t)bh * SEQ + q0 + w * 16) * HD;
        const float* r0 = Qg + (size_t)g * HD;
        const float* r1 = Qg + (size_t)(g + 8) * HD;
#pragma unroll
        for (int t = 0; t < 8; t++) {
            qf[t][0] = cvt_tf32(r0[8 * t + m]);
            qf[t][1] = cvt_tf32(r1[8 * t + m]);
            qf[t][2] = cvt_tf32(r0[8 * t + m + 4]);
            qf[t][3] = cvt_tf32(r1[8 * t + m + 4]);
        }
    }

    float mr0 = -1e30f, mr1 = -1e30f;   // running max, rows g and g+8
    float lr0 = 0.f,    lr1 = 0.f;      // running sum
    float oa[8][4];
#pragma unroll
    for (int d = 0; d < 8; d++)
#pragma unroll
        for (int i = 0; i < 4; i++) oa[d][i] = 0.f;

    const float* Kg    = g_K + (size_t)bh * SEQ * HD;
    const float* Vg    = g_V + (size_t)bh * SEQ * HD;
    const float* biasg = attn_bias + (size_t)bh * SEQ;

    for (int k0 = 0; k0 < SEQ; k0 += 64) {
        __syncthreads();
        // ---- Load K,V tile (64x64) -> smem, converted to tf32 ----
        {
            int r = tid >> 1;                 // 0..63
            int c0 = (tid & 1) * 32;          // 0 or 32
            const float* kp = Kg + (size_t)(k0 + r) * HD + c0;
            const float* vp = Vg + (size_t)(k0 + r) * HD + c0;
#pragma unroll
            for (int u = 0; u < 8; u++) {
                float4 kv = ((const float4*)kp)[u];
                float4 vv = ((const float4*)vp)[u];
                int c = c0 + 4 * u;
                Ks[r][c + 0] = __uint_as_float(cvt_tf32(kv.x));
                Ks[r][c + 1] = __uint_as_float(cvt_tf32(kv.y));
                Ks[r][c + 2] = __uint_as_float(cvt_tf32(kv.z));
                Ks[r][c + 3] = __uint_as_float(cvt_tf32(kv.w));
                Vs[r][c + 0] = __uint_as_float(cvt_tf32(vv.x));
                Vs[r][c + 1] = __uint_as_float(cvt_tf32(vv.y));
                Vs[r][c + 2] = __uint_as_float(cvt_tf32(vv.z));
                Vs[r][c + 3] = __uint_as_float(cvt_tf32(vv.w));
            }
            if (tid < 64) biasS[tid] = beta * biasg[k0 + tid] + bbias;
        }
        __syncthreads();

        // ---- Scores: sc[j] = Q(16x64) . K^T(64x8) for key block j ----
        float sc[8][4];
#pragma unroll
        for (int j = 0; j < 8; j++)
#pragma unroll
            for (int i = 0; i < 4; i++) sc[j][i] = 0.f;

#pragma unroll
        for (int t = 0; t < 8; t++) {       // k-dim chunks (d)
#pragma unroll
            for (int j = 0; j < 8; j++) {   // key blocks (independent accums)
                unsigned b0 = __float_as_uint(Ks[8 * j + g][8 * t + m]);
                unsigned b1 = __float_as_uint(Ks[8 * j + g][8 * t + m + 4]);
                mma_tf32(sc[j], qf[t], b0, b1);
            }
        }

        // ---- bias (+mask) ----
#pragma unroll
        for (int j = 0; j < 8; j++) {
            int key = 8 * j + 2 * m;
            float b0v = biasS[key], b1v = biasS[key + 1];
            sc[j][0] += b0v; sc[j][1] += b1v;
            sc[j][2] += b0v; sc[j][3] += b1v;
            if (masknz) {
                int qr = q0 + w * 16 + g;
                const float* m0p = mask + ((size_t)b * SEQ + qr) * SEQ + k0 + key;
                const float* m1p = m0p + (size_t)8 * SEQ;
                sc[j][0] += m0p[0]; sc[j][1] += m0p[1];
                sc[j][2] += m1p[0]; sc[j][3] += m1p[1];
            }
        }

        // ---- Online softmax (rows g and g+8, reduced across the quad) ----
        float mx0 = sc[0][0], mx1 = sc[0][2];
#pragma unroll
        for (int j = 0; j < 8; j++) {
            mx0 = fmaxf(mx0, fmaxf(sc[j][0], sc[j][1]));
            mx1 = fmaxf(mx1, fmaxf(sc[j][2], sc[j][3]));
        }
        mx0 = fmaxf(mx0, __shfl_xor_sync(0xffffffffu, mx0, 1));
        mx0 = fmaxf(mx0, __shfl_xor_sync(0xffffffffu, mx0, 2));
        mx1 = fmaxf(mx1, __shfl_xor_sync(0xffffffffu, mx1, 1));
        mx1 = fmaxf(mx1, __shfl_xor_sync(0xffffffffu, mx1, 2));

        float mn0 = fmaxf(mr0, mx0);
        float mn1 = fmaxf(mr1, mx1);
        float al0 = __expf(mr0 - mn0);
        float al1 = __expf(mr1 - mn1);

        float s0 = 0.f, s1 = 0.f;
#pragma unroll
        for (int j = 0; j < 8; j++) {
            sc[j][0] = __expf(sc[j][0] - mn0);
            sc[j][1] = __expf(sc[j][1] - mn0);
            sc[j][2] = __expf(sc[j][2] - mn1);
            sc[j][3] = __expf(sc[j][3] - mn1);
            s0 += sc[j][0] + sc[j][1];
            s1 += sc[j][2] + sc[j][3];
        }
        s0 += __shfl_xor_sync(0xffffffffu, s0, 1);
        s0 += __shfl_xor_sync(0xffffffffu, s0, 2);
        s1 += __shfl_xor_sync(0xffffffffu, s1, 1);
        s1 += __shfl_xor_sync(0xffffffffu, s1, 2);

        lr0 = lr0 * al0 + s0;
        lr1 = lr1 * al1 + s1;
        mr0 = mn0; mr1 = mn1;
#pragma unroll
        for (int d = 0; d < 8; d++) {
            oa[d][0] *= al0; oa[d][1] *= al0;
            oa[d][2] *= al1; oa[d][3] *= al1;
        }

        // ---- PV: convert P C-layout -> A-layout (width-4 shuffles), mma ----
        int src0 = (lane & ~3) | (m >> 1);
        int src1 = src0 + 2;
        int sel  = m & 1;
#pragma unroll
        for (int j = 0; j < 8; j++) {
            unsigned p0 = cvt_tf32(sc[j][0]);
            unsigned p1 = cvt_tf32(sc[j][1]);
            unsigned p2 = cvt_tf32(sc[j][2]);
            unsigned p3 = cvt_tf32(sc[j][3]);
            unsigned pa[4];
            {
                unsigned x0 = __shfl_sync(0xffffffffu, p0, src0);
                unsigned x1 = __shfl_sync(0xffffffffu, p1, src0);
                pa[0] = sel ? x1 : x0;                    // (row g,   col m)
                unsigned x2 = __shfl_sync(0xffffffffu, p2, src0);
                unsigned x3 = __shfl_sync(0xffffffffu, p3, src0);
                pa[1] = sel ? x3 : x2;                    // (row g+8, col m)
                unsigned y0 = __shfl_sync(0xffffffffu, p0, src1);
                unsigned y1 = __shfl_sync(0xffffffffu, p1, src1);
                pa[2] = sel ? y1 : y0;                    // (row g,   col m+4)
                unsigned y2 = __shfl_sync(0xffffffffu, p2, src1);
                unsigned y3 = __shfl_sync(0xffffffffu, p3, src1);
                pa[3] = sel ? y3 : y2;                    // (row g+8, col m+4)
            }
#pragma unroll
            for (int d = 0; d < 8; d++) {
                unsigned b0 = __float_as_uint(Vs[8 * j + m][8 * d + g]);
                unsigned b1 = __float_as_uint(Vs[8 * j + m + 4][8 * d + g]);
                mma_tf32(oa[d], pa, b0, b1);
            }
        }
    }

    // ---- Epilogue: normalize, write to g_O[token][h*64 + d] ----
    float inv0 = 1.f / lr0;
    float inv1 = 1.f / lr1;
    int qr = q0 + w * 16 + g;
    float* O0 = g_O + ((size_t)(b * SEQ + qr)) * EMB + h * HD;
    float* O1 = O0 + (size_t)8 * EMB;
#pragma unroll
    for (int d = 0; d < 8; d++) {
        int c = 8 * d + 2 * m;
        float2 v0 = make_float2(oa[d][0] * inv0, oa[d][1] * inv0);
        float2 v1 = make_float2(oa[d][2] * inv1, oa[d][3] * inv1);
        *(float2*)(O0 + c) = v0;
        *(float2*)(O1 + c) = v1;
    }
}

// ---------------------------------------------------------------------------
// Launch
// ---------------------------------------------------------------------------
extern "C" void kernel_launch(void* const* d_in, const int* in_sizes, int n_in,
                              void* d_out, int out_size) {
    const float* X     = (const float*)d_in[0];
    const float* mask  = (const float*)d_in[1];
    const float* abias = (const float*)d_in[2];
    const float* Wq    = (const float*)d_in[3];
    const float* bq    = (const float*)d_in[4];
    const float* Wk    = (const float*)d_in[5];
    const float* bk    = (const float*)d_in[6];
    const float* Wv    = (const float*)d_in[7];
    const float* bv    = (const float*)d_in[8];
    const float* Wo    = (const float*)d_in[9];
    const float* bo    = (const float*)d_in[10];
    const float* beta  = (const float*)d_in[11];
    const float* bbias = (const float*)d_in[12];
    float* out = (float*)d_out;

    reset_flag_kernel<<<1, 32>>>();
    scan_mask_kernel<<<1024, 256>>>(mask, BSZ * SEQ * SEQ / 4);
    qkv_gemm_kernel<<<dim3(18, 32), 256>>>(X, Wq, bq, Wk, bk, Wv, bv);
    attn_tc_kernel<<<dim3(SEQ / 64, BH), 128>>>(mask, abias, beta, bbias);
    oproj_gemm_kernel<<<dim3(6, 32), 256>>>(Wo, bo, out);
}

// round 3
// speedup vs baseline: 3.2886x; 1.3507x over previous
#include <cuda_runtime.h>
#include <math.h>

#define BSZ 2
#define SEQ 2048
#define EMB 768
#define NH  12
#define HD  64
#define BH  (BSZ*NH)     /* 24  */
#define MTOK (BSZ*SEQ)   /* 4096 */

// ---------------------------------------------------------------------------
// Scratch
// ---------------------------------------------------------------------------
__device__ float g_Q[BH * SEQ * HD];
__device__ float g_K[BH * SEQ * HD];
__device__ float g_V[BH * SEQ * HD];
__device__ float g_O[MTOK * EMB];
__device__ int   g_mask_nz;

// ---------------------------------------------------------------------------
// Mask scan
// ---------------------------------------------------------------------------
__global__ void reset_flag_kernel() { g_mask_nz = 0; }

__global__ void scan_mask_kernel(const float* __restrict__ mask, int n4) {
    int i = blockIdx.x * blockDim.x + threadIdx.x;
    int stride = gridDim.x * blockDim.x;
    int nz = 0;
    for (; i < n4; i += stride) {
        float4 v = ((const float4*)mask)[i];
        nz |= (v.x != 0.f) | (v.y != 0.f) | (v.z != 0.f) | (v.w != 0.f);
    }
    if (__syncthreads_or(nz)) {
        if (threadIdx.x == 0) atomicOr(&g_mask_nz, 1);
    }
}

// ---------------------------------------------------------------------------
// tf32 helpers
// ---------------------------------------------------------------------------
__device__ __forceinline__ unsigned cvt_tf32(float x) {
    unsigned r;
    asm("cvt.rna.tf32.f32 %0, %1;" : "=r"(r) : "f"(x));
    return r;
}
__device__ __forceinline__ float cvt_tf32_f(float x) {
    return __uint_as_float(cvt_tf32(x));
}

__device__ __forceinline__ void mma_tf32(float c[4], const unsigned a[4],
                                         unsigned b0, unsigned b1) {
    asm("mma.sync.aligned.m16n8k8.row.col.f32.tf32.tf32.f32 "
        "{%0,%1,%2,%3},{%4,%5,%6,%7},{%8,%9},{%0,%1,%2,%3};"
        : "+f"(c[0]), "+f"(c[1]), "+f"(c[2]), "+f"(c[3])
        : "r"(a[0]), "r"(a[1]), "r"(a[2]), "r"(a[3]), "r"(b0), "r"(b1));
}

// ---------------------------------------------------------------------------
// tf32 tensor-core GEMM core: C(128x128) = A(128xK) @ W^T(128xK)
// 256 threads = 8 warps (warp grid 4m x 2n), warp tile 32x64.
// Smem perm layout: element k=8t+m' at pos = (m'&3)*8 + t*2 + (m'>>2),
// row stride 34 floats -> A/B fragments are single LDS.64, <=2-way banks.
// ---------------------------------------------------------------------------
#define GSW 34   /* smem row stride (floats) */

struct GemmAcc { float a[2][8][4]; };

__device__ __forceinline__ void gemm_tile_tf32(
    const float* __restrict__ A,   // [.. x EMB], row base bm
    const float* __restrict__ W,   // [.. x EMB], row base bn
    int bm, int bn, GemmAcc& acc,
    float* As, float* Bs)
{
    int tid = threadIdx.x;
    int lane = tid & 31;
    int wid = tid >> 5;
    int g = lane >> 2, m = lane & 3;
    int wm = wid & 3, wn = wid >> 2;

#pragma unroll
    for (int im = 0; im < 2; im++)
#pragma unroll
        for (int jn = 0; jn < 8; jn++)
#pragma unroll
            for (int i = 0; i < 4; i++) acc.a[im][jn][i] = 0.f;

    int row = tid >> 1;
    int c0  = (tid & 1) * 16;
    const float* ap = A + (size_t)(bm + row) * EMB + c0;
    const float* bp = W + (size_t)(bn + row) * EMB + c0;
    float* arow = As + row * GSW;
    float* brow = Bs + row * GSW;

    for (int k0 = 0; k0 < EMB; k0 += 32) {
#pragma unroll
        for (int u = 0; u < 4; u++) {
            int c = c0 + 4 * u;
            int t = c >> 3, half = (c >> 2) & 1;
            int pb = t * 2 + half;
            float4 va = *(const float4*)(ap + k0 + 4 * u);
            arow[pb + 0]  = cvt_tf32_f(va.x);
            arow[pb + 8]  = cvt_tf32_f(va.y);
            arow[pb + 16] = cvt_tf32_f(va.z);
            arow[pb + 24] = cvt_tf32_f(va.w);
            float4 vb = *(const float4*)(bp + k0 + 4 * u);
            brow[pb + 0]  = cvt_tf32_f(vb.x);
            brow[pb + 8]  = cvt_tf32_f(vb.y);
            brow[pb + 16] = cvt_tf32_f(vb.z);
            brow[pb + 24] = cvt_tf32_f(vb.w);
        }
        __syncthreads();

#pragma unroll
        for (int t = 0; t < 4; t++) {
            unsigned af[2][4];
#pragma unroll
            for (int im = 0; im < 2; im++) {
                const float* base = As + (wm * 32 + im * 16) * GSW + m * 8 + t * 2;
                float2 lo = *(const float2*)(base + g * GSW);
                float2 hi = *(const float2*)(base + (g + 8) * GSW);
                af[im][0] = __float_as_uint(lo.x);
                af[im][1] = __float_as_uint(hi.x);
                af[im][2] = __float_as_uint(lo.y);
                af[im][3] = __float_as_uint(hi.y);
            }
#pragma unroll
            for (int jn = 0; jn < 8; jn++) {
                float2 bv = *(const float2*)(Bs + (wn * 64 + jn * 8 + g) * GSW + m * 8 + t * 2);
                unsigned b0 = __float_as_uint(bv.x);
                unsigned b1 = __float_as_uint(bv.y);
                mma_tf32(acc.a[0][jn], af[0], b0, b1);
                mma_tf32(acc.a[1][jn], af[1], b0, b1);
            }
        }
        __syncthreads();
    }
}

// ---------------------------------------------------------------------------
// QKV projection: grid (18, 32). x: seg(3) x nblock(6); y: mblock.
// Writes [bh][s][d] layout, Q scaled by 0.125.
// ---------------------------------------------------------------------------
__global__ void __launch_bounds__(256) qkv_gemm_tc_kernel(
    const float* __restrict__ X,
    const float* __restrict__ Wq, const float* __restrict__ bq,
    const float* __restrict__ Wk, const float* __restrict__ bk,
    const float* __restrict__ Wv, const float* __restrict__ bv)
{
    __shared__ __align__(16) float As[128 * GSW];
    __shared__ __align__(16) float Bs[128 * GSW];

    int bx  = blockIdx.x;
    int seg = bx / 6;
    int nb  = bx % 6;
    int bm  = blockIdx.y * 128;

    const float* W    = (seg == 0) ? Wq : (seg == 1) ? Wk : Wv;
    const float* bias = (seg == 0) ? bq : (seg == 1) ? bk : bv;
    float*       out  = (seg == 0) ? g_Q : (seg == 1) ? g_K : g_V;
    const float scale = (seg == 0) ? 0.125f : 1.0f;

    GemmAcc acc;
    gemm_tile_tf32(X, W, bm, nb * 128, acc, As, Bs);

    int lane = threadIdx.x & 31;
    int wid  = threadIdx.x >> 5;
    int g = lane >> 2, m = lane & 3;
    int wm = wid & 3, wn = wid >> 2;

#pragma unroll
    for (int im = 0; im < 2; im++) {
        int r0 = bm + wm * 32 + im * 16 + g;
#pragma unroll
        for (int jn = 0; jn < 8; jn++) {
            int nloc = nb * 128 + wn * 64 + jn * 8 + 2 * m;  // 0..767
            int h = nloc >> 6, d = nloc & 63;
            float b0v = bias[nloc], b1v = bias[nloc + 1];
            int b = r0 >> 11, s0 = r0 & 2047;
            float* o0 = out + ((size_t)((b * NH + h) * SEQ + s0)) * HD + d;
            float* o1 = o0 + (size_t)8 * HD;
            float2 v0 = make_float2((acc.a[im][jn][0] + b0v) * scale,
                                    (acc.a[im][jn][1] + b1v) * scale);
            float2 v1 = make_float2((acc.a[im][jn][2] + b0v) * scale,
                                    (acc.a[im][jn][3] + b1v) * scale);
            *(float2*)o0 = v0;
            *(float2*)o1 = v1;
        }
    }
}

// ---------------------------------------------------------------------------
// Output projection: grid (6, 32). d_out = g_O @ Wo^T + bo, row-major.
// ---------------------------------------------------------------------------
__global__ void __launch_bounds__(256) oproj_gemm_tc_kernel(
    const float* __restrict__ W, const float* __restrict__ bias,
    float* __restrict__ C)
{
    __shared__ __align__(16) float As[128 * GSW];
    __shared__ __align__(16) float Bs[128 * GSW];

    int bn = blockIdx.x * 128;
    int bm = blockIdx.y * 128;

    GemmAcc acc;
    gemm_tile_tf32(g_O, W, bm, bn, acc, As, Bs);

    int lane = threadIdx.x & 31;
    int wid  = threadIdx.x >> 5;
    int g = lane >> 2, m = lane & 3;
    int wm = wid & 3, wn = wid >> 2;

#pragma unroll
    for (int im = 0; im < 2; im++) {
        int r0 = bm + wm * 32 + im * 16 + g;
#pragma unroll
        for (int jn = 0; jn < 8; jn++) {
            int n = bn + wn * 64 + jn * 8 + 2 * m;
            float b0v = bias[n], b1v = bias[n + 1];
            float* o0 = C + (size_t)r0 * EMB + n;
            float* o1 = o0 + (size_t)8 * EMB;
            *(float2*)o0 = make_float2(acc.a[im][jn][0] + b0v, acc.a[im][jn][1] + b1v);
            *(float2*)o1 = make_float2(acc.a[im][jn][2] + b0v, acc.a[im][jn][3] + b1v);
        }
    }
}

// ---------------------------------------------------------------------------
// Tensor-core flash attention (tf32) — unchanged from R2 (proven 481us).
// ---------------------------------------------------------------------------
__global__ void __launch_bounds__(128) attn_tc_kernel(
    const float* __restrict__ mask,
    const float* __restrict__ attn_bias,
    const float* __restrict__ beta_p,
    const float* __restrict__ bbias_p)
{
    __shared__ float Ks[64][68];
    __shared__ float Vs[64][72];
    __shared__ float biasS[64];

    int qt   = blockIdx.x;
    int bh   = blockIdx.y;
    int b    = bh / NH;
    int h    = bh % NH;
    int q0   = qt * 64;
    int tid  = threadIdx.x;
    int w    = tid >> 5;
    int lane = tid & 31;
    int g    = lane >> 2;
    int m    = lane & 3;

    const float beta  = beta_p[0];
    const float bbias = bbias_p[0];
    const int masknz  = g_mask_nz;

    unsigned qf[8][4];
    {
        const float* Qg = g_Q + ((size_t)bh * SEQ + q0 + w * 16) * HD;
        const float* r0 = Qg + (size_t)g * HD;
        const float* r1 = Qg + (size_t)(g + 8) * HD;
#pragma unroll
        for (int t = 0; t < 8; t++) {
            qf[t][0] = cvt_tf32(r0[8 * t + m]);
            qf[t][1] = cvt_tf32(r1[8 * t + m]);
            qf[t][2] = cvt_tf32(r0[8 * t + m + 4]);
            qf[t][3] = cvt_tf32(r1[8 * t + m + 4]);
        }
    }

    float mr0 = -1e30f, mr1 = -1e30f;
    float lr0 = 0.f,    lr1 = 0.f;
    float oa[8][4];
#pragma unroll
    for (int d = 0; d < 8; d++)
#pragma unroll
        for (int i = 0; i < 4; i++) oa[d][i] = 0.f;

    const float* Kg    = g_K + (size_t)bh * SEQ * HD;
    const float* Vg    = g_V + (size_t)bh * SEQ * HD;
    const float* biasg = attn_bias + (size_t)bh * SEQ;

    for (int k0 = 0; k0 < SEQ; k0 += 64) {
        __syncthreads();
        {
            int r = tid >> 1;
            int c0 = (tid & 1) * 32;
            const float* kp = Kg + (size_t)(k0 + r) * HD + c0;
            const float* vp = Vg + (size_t)(k0 + r) * HD + c0;
#pragma unroll
            for (int u = 0; u < 8; u++) {
                float4 kv = ((const float4*)kp)[u];
                float4 vv = ((const float4*)vp)[u];
                int c = c0 + 4 * u;
                Ks[r][c + 0] = cvt_tf32_f(kv.x);
                Ks[r][c + 1] = cvt_tf32_f(kv.y);
                Ks[r][c + 2] = cvt_tf32_f(kv.z);
                Ks[r][c + 3] = cvt_tf32_f(kv.w);
                Vs[r][c + 0] = cvt_tf32_f(vv.x);
                Vs[r][c + 1] = cvt_tf32_f(vv.y);
                Vs[r][c + 2] = cvt_tf32_f(vv.z);
                Vs[r][c + 3] = cvt_tf32_f(vv.w);
            }
            if (tid < 64) biasS[tid] = beta * biasg[k0 + tid] + bbias;
        }
        __syncthreads();

        float sc[8][4];
#pragma unroll
        for (int j = 0; j < 8; j++)
#pragma unroll
            for (int i = 0; i < 4; i++) sc[j][i] = 0.f;

#pragma unroll
        for (int t = 0; t < 8; t++) {
#pragma unroll
            for (int j = 0; j < 8; j++) {
                unsigned b0 = __float_as_uint(Ks[8 * j + g][8 * t + m]);
                unsigned b1 = __float_as_uint(Ks[8 * j + g][8 * t + m + 4]);
                mma_tf32(sc[j], qf[t], b0, b1);
            }
        }

#pragma unroll
        for (int j = 0; j < 8; j++) {
            int key = 8 * j + 2 * m;
            float b0v = biasS[key], b1v = biasS[key + 1];
            sc[j][0] += b0v; sc[j][1] += b1v;
            sc[j][2] += b0v; sc[j][3] += b1v;
            if (masknz) {
                int qr = q0 + w * 16 + g;
                const float* m0p = mask + ((size_t)b * SEQ + qr) * SEQ + k0 + key;
                const float* m1p = m0p + (size_t)8 * SEQ;
                sc[j][0] += m0p[0]; sc[j][1] += m0p[1];
                sc[j][2] += m1p[0]; sc[j][3] += m1p[1];
            }
        }

        float mx0 = sc[0][0], mx1 = sc[0][2];
#pragma unroll
        for (int j = 0; j < 8; j++) {
            mx0 = fmaxf(mx0, fmaxf(sc[j][0], sc[j][1]));
            mx1 = fmaxf(mx1, fmaxf(sc[j][2], sc[j][3]));
        }
        mx0 = fmaxf(mx0, __shfl_xor_sync(0xffffffffu, mx0, 1));
        mx0 = fmaxf(mx0, __shfl_xor_sync(0xffffffffu, mx0, 2));
        mx1 = fmaxf(mx1, __shfl_xor_sync(0xffffffffu, mx1, 1));
        mx1 = fmaxf(mx1, __shfl_xor_sync(0xffffffffu, mx1, 2));

        float mn0 = fmaxf(mr0, mx0);
        float mn1 = fmaxf(mr1, mx1);
        float al0 = __expf(mr0 - mn0);
        float al1 = __expf(mr1 - mn1);

        float s0 = 0.f, s1 = 0.f;
#pragma unroll
        for (int j = 0; j < 8; j++) {
            sc[j][0] = __expf(sc[j][0] - mn0);
            sc[j][1] = __expf(sc[j][1] - mn0);
            sc[j][2] = __expf(sc[j][2] - mn1);
            sc[j][3] = __expf(sc[j][3] - mn1);
            s0 += sc[j][0] + sc[j][1];
            s1 += sc[j][2] + sc[j][3];
        }
        s0 += __shfl_xor_sync(0xffffffffu, s0, 1);
        s0 += __shfl_xor_sync(0xffffffffu, s0, 2);
        s1 += __shfl_xor_sync(0xffffffffu, s1, 1);
        s1 += __shfl_xor_sync(0xffffffffu, s1, 2);

        lr0 = lr0 * al0 + s0;
        lr1 = lr1 * al1 + s1;
        mr0 = mn0; mr1 = mn1;
#pragma unroll
        for (int d = 0; d < 8; d++) {
            oa[d][0] *= al0; oa[d][1] *= al0;
            oa[d][2] *= al1; oa[d][3] *= al1;
        }

        int src0 = (lane & ~3) | (m >> 1);
        int src1 = src0 + 2;
        int sel  = m & 1;
#pragma unroll
        for (int j = 0; j < 8; j++) {
            unsigned p0 = cvt_tf32(sc[j][0]);
            unsigned p1 = cvt_tf32(sc[j][1]);
            unsigned p2 = cvt_tf32(sc[j][2]);
            unsigned p3 = cvt_tf32(sc[j][3]);
            unsigned pa[4];
            {
                unsigned x0 = __shfl_sync(0xffffffffu, p0, src0);
                unsigned x1 = __shfl_sync(0xffffffffu, p1, src0);
                pa[0] = sel ? x1 : x0;
                unsigned x2 = __shfl_sync(0xffffffffu, p2, src0);
                unsigned x3 = __shfl_sync(0xffffffffu, p3, src0);
                pa[1] = sel ? x3 : x2;
                unsigned y0 = __shfl_sync(0xffffffffu, p0, src1);
                unsigned y1 = __shfl_sync(0xffffffffu, p1, src1);
                pa[2] = sel ? y1 : y0;
                unsigned y2 = __shfl_sync(0xffffffffu, p2, src1);
                unsigned y3 = __shfl_sync(0xffffffffu, p3, src1);
                pa[3] = sel ? y3 : y2;
            }
#pragma unroll
            for (int d = 0; d < 8; d++) {
                unsigned b0 = __float_as_uint(Vs[8 * j + m][8 * d + g]);
                unsigned b1 = __float_as_uint(Vs[8 * j + m + 4][8 * d + g]);
                mma_tf32(oa[d], pa, b0, b1);
            }
        }
    }

    float inv0 = 1.f / lr0;
    float inv1 = 1.f / lr1;
    int qr = q0 + w * 16 + g;
    float* O0 = g_O + ((size_t)(b * SEQ + qr)) * EMB + h * HD;
    float* O1 = O0 + (size_t)8 * EMB;
#pragma unroll
    for (int d = 0; d < 8; d++) {
        int c = 8 * d + 2 * m;
        *(float2*)(O0 + c) = make_float2(oa[d][0] * inv0, oa[d][1] * inv0);
        *(float2*)(O1 + c) = make_float2(oa[d][2] * inv1, oa[d][3] * inv1);
    }
}

// ---------------------------------------------------------------------------
// Launch
// ---------------------------------------------------------------------------
extern "C" void kernel_launch(void* const* d_in, const int* in_sizes, int n_in,
                              void* d_out, int out_size) {
    const float* X     = (const float*)d_in[0];
    const float* mask  = (const float*)d_in[1];
    const float* abias = (const float*)d_in[2];
    const float* Wq    = (const float*)d_in[3];
    const float* bq    = (const float*)d_in[4];
    const float* Wk    = (const float*)d_in[5];
    const float* bk    = (const float*)d_in[6];
    const float* Wv    = (const float*)d_in[7];
    const float* bv    = (const float*)d_in[8];
    const float* Wo    = (const float*)d_in[9];
    const float* bo    = (const float*)d_in[10];
    const float* beta  = (const float*)d_in[11];
    const float* bbias = (const float*)d_in[12];
    float* out = (float*)d_out;

    reset_flag_kernel<<<1, 32>>>();
    scan_mask_kernel<<<1024, 256>>>(mask, BSZ * SEQ * SEQ / 4);
    qkv_gemm_tc_kernel<<<dim3(18, 32), 256>>>(X, Wq, bq, Wk, bk, Wv, bv);
    attn_tc_kernel<<<dim3(SEQ / 64, BH), 128>>>(mask, abias, beta, bbias);
    oproj_gemm_tc_kernel<<<dim3(6, 32), 256>>>(Wo, bo, out);
}

// round 6
// speedup vs baseline: 5.2623x; 1.6002x over previous
#include <cuda_runtime.h>
#include <stdint.h>
#include <math.h>

#define BSZ 2
#define SEQ 2048
#define EMB 768
#define NH  12
#define HD  64
#define BH  (BSZ*NH)     /* 24  */
#define MTOK (BSZ*SEQ)   /* 4096 */

// ---------------------------------------------------------------------------
// Scratch
// ---------------------------------------------------------------------------
__device__ float g_Q[BH * SEQ * HD];
__device__ float g_K[BH * SEQ * HD];
__device__ float g_V[BH * SEQ * HD];
__device__ float g_O[MTOK * EMB];
__device__ int   g_mask_nz;

// ---------------------------------------------------------------------------
// Mask scan
// ---------------------------------------------------------------------------
__global__ void reset_flag_kernel() { g_mask_nz = 0; }

__global__ void scan_mask_kernel(const float* __restrict__ mask, int n4) {
    int i = blockIdx.x * blockDim.x + threadIdx.x;
    int stride = gridDim.x * blockDim.x;
    int nz = 0;
    for (; i < n4; i += stride) {
        float4 v = ((const float4*)mask)[i];
        nz |= (v.x != 0.f) | (v.y != 0.f) | (v.z != 0.f) | (v.w != 0.f);
    }
    if (__syncthreads_or(nz)) {
        if (threadIdx.x == 0) atomicOr(&g_mask_nz, 1);
    }
}

// ---------------------------------------------------------------------------
// tf32 / cp.async helpers
// ---------------------------------------------------------------------------
__device__ __forceinline__ unsigned cvt_tf32(float x) {
    unsigned r;
    asm("cvt.rna.tf32.f32 %0, %1;" : "=r"(r) : "f"(x));
    return r;
}
__device__ __forceinline__ float cvt_tf32_f(float x) {
    return __uint_as_float(cvt_tf32(x));
}

__device__ __forceinline__ void mma_tf32(float c[4], const unsigned a[4],
                                         unsigned b0, unsigned b1) {
    asm("mma.sync.aligned.m16n8k8.row.col.f32.tf32.tf32.f32 "
        "{%0,%1,%2,%3},{%4,%5,%6,%7},{%8,%9},{%0,%1,%2,%3};"
        : "+f"(c[0]), "+f"(c[1]), "+f"(c[2]), "+f"(c[3])
        : "r"(a[0]), "r"(a[1]), "r"(a[2]), "r"(a[3]), "r"(b0), "r"(b1));
}

__device__ __forceinline__ void cp_async16(unsigned saddr, const void* gptr) {
    asm volatile("cp.async.cg.shared.global [%0], [%1], 16;"
                 :: "r"(saddr), "l"(gptr));
}
__device__ __forceinline__ void cp_commit() {
    asm volatile("cp.async.commit_group;");
}
template <int N>
__device__ __forceinline__ void cp_wait() {
    asm volatile("cp.async.wait_group %0;" :: "n"(N));
}

// ---------------------------------------------------------------------------
// tf32 tensor-core GEMM core: C(128x128) = A(128xK) @ W^T(128xK)
// ---------------------------------------------------------------------------
#define GSW 34

struct GemmAcc { float a[2][8][4]; };

__device__ __forceinline__ void gemm_tile_tf32(
    const float* __restrict__ A,
    const float* __restrict__ W,
    int bm, int bn, GemmAcc& acc,
    float* As, float* Bs)
{
    int tid = threadIdx.x;
    int lane = tid & 31;
    int wid = tid >> 5;
    int g = lane >> 2, m = lane & 3;
    int wm = wid & 3, wn = wid >> 2;

#pragma unroll
    for (int im = 0; im < 2; im++)
#pragma unroll
        for (int jn = 0; jn < 8; jn++)
#pragma unroll
            for (int i = 0; i < 4; i++) acc.a[im][jn][i] = 0.f;

    int row = tid >> 1;
    int c0  = (tid & 1) * 16;
    const float* ap = A + (size_t)(bm + row) * EMB + c0;
    const float* bp = W + (size_t)(bn + row) * EMB + c0;
    float* arow = As + row * GSW;
    float* brow = Bs + row * GSW;

    for (int k0 = 0; k0 < EMB; k0 += 32) {
#pragma unroll
        for (int u = 0; u < 4; u++) {
            int c = c0 + 4 * u;
            int t = c >> 3, half = (c >> 2) & 1;
            int pb = t * 2 + half;
            float4 va = *(const float4*)(ap + k0 + 4 * u);
            arow[pb + 0]  = cvt_tf32_f(va.x);
            arow[pb + 8]  = cvt_tf32_f(va.y);
            arow[pb + 16] = cvt_tf32_f(va.z);
            arow[pb + 24] = cvt_tf32_f(va.w);
            float4 vb = *(const float4*)(bp + k0 + 4 * u);
            brow[pb + 0]  = cvt_tf32_f(vb.x);
            brow[pb + 8]  = cvt_tf32_f(vb.y);
            brow[pb + 16] = cvt_tf32_f(vb.z);
            brow[pb + 24] = cvt_tf32_f(vb.w);
        }
        __syncthreads();

#pragma unroll
        for (int t = 0; t < 4; t++) {
            unsigned af[2][4];
#pragma unroll
            for (int im = 0; im < 2; im++) {
                const float* base = As + (wm * 32 + im * 16) * GSW + m * 8 + t * 2;
                float2 lo = *(const float2*)(base + g * GSW);
                float2 hi = *(const float2*)(base + (g + 8) * GSW);
                af[im][0] = __float_as_uint(lo.x);
                af[im][1] = __float_as_uint(hi.x);
                af[im][2] = __float_as_uint(lo.y);
                af[im][3] = __float_as_uint(hi.y);
            }
#pragma unroll
            for (int jn = 0; jn < 8; jn++) {
                float2 bv = *(const float2*)(Bs + (wn * 64 + jn * 8 + g) * GSW + m * 8 + t * 2);
                unsigned b0 = __float_as_uint(bv.x);
                unsigned b1 = __float_as_uint(bv.y);
                mma_tf32(acc.a[0][jn], af[0], b0, b1);
                mma_tf32(acc.a[1][jn], af[1], b0, b1);
            }
        }
        __syncthreads();
    }
}

// ---------------------------------------------------------------------------
// QKV projection. Epilogue stores tf32-rounded values so the attention
// kernel can feed smem data straight to mma (truncation exact).
// ---------------------------------------------------------------------------
__global__ void __launch_bounds__(256) qkv_gemm_tc_kernel(
    const float* __restrict__ X,
    const float* __restrict__ Wq, const float* __restrict__ bq,
    const float* __restrict__ Wk, const float* __restrict__ bk,
    const float* __restrict__ Wv, const float* __restrict__ bv)
{
    __shared__ __align__(16) float As[128 * GSW];
    __shared__ __align__(16) float Bs[128 * GSW];

    int bx  = blockIdx.x;
    int seg = bx / 6;
    int nb  = bx % 6;
    int bm  = blockIdx.y * 128;

    const float* W    = (seg == 0) ? Wq : (seg == 1) ? Wk : Wv;
    const float* bias = (seg == 0) ? bq : (seg == 1) ? bk : bv;
    float*       out  = (seg == 0) ? g_Q : (seg == 1) ? g_K : g_V;
    const float scale = (seg == 0) ? 0.125f : 1.0f;

    GemmAcc acc;
    gemm_tile_tf32(X, W, bm, nb * 128, acc, As, Bs);

    int lane = threadIdx.x & 31;
    int wid  = threadIdx.x >> 5;
    int g = lane >> 2, m = lane & 3;
    int wm = wid & 3, wn = wid >> 2;

#pragma unroll
    for (int im = 0; im < 2; im++) {
        int r0 = bm + wm * 32 + im * 16 + g;
#pragma unroll
        for (int jn = 0; jn < 8; jn++) {
            int nloc = nb * 128 + wn * 64 + jn * 8 + 2 * m;
            int h = nloc >> 6, d = nloc & 63;
            float b0v = bias[nloc], b1v = bias[nloc + 1];
            int b = r0 >> 11, s0 = r0 & 2047;
            float* o0 = out + ((size_t)((b * NH + h) * SEQ + s0)) * HD + d;
            float* o1 = o0 + (size_t)8 * HD;
            *(float2*)o0 = make_float2(cvt_tf32_f((acc.a[im][jn][0] + b0v) * scale),
                                       cvt_tf32_f((acc.a[im][jn][1] + b1v) * scale));
            *(float2*)o1 = make_float2(cvt_tf32_f((acc.a[im][jn][2] + b0v) * scale),
                                       cvt_tf32_f((acc.a[im][jn][3] + b1v) * scale));
        }
    }
}

// ---------------------------------------------------------------------------
// Output projection
// ---------------------------------------------------------------------------
__global__ void __launch_bounds__(256) oproj_gemm_tc_kernel(
    const float* __restrict__ W, const float* __restrict__ bias,
    float* __restrict__ C)
{
    __shared__ __align__(16) float As[128 * GSW];
    __shared__ __align__(16) float Bs[128 * GSW];

    int bn = blockIdx.x * 128;
    int bm = blockIdx.y * 128;

    GemmAcc acc;
    gemm_tile_tf32(g_O, W, bm, bn, acc, As, Bs);

    int lane = threadIdx.x & 31;
    int wid  = threadIdx.x >> 5;
    int g = lane >> 2, m = lane & 3;
    int wm = wid & 3, wn = wid >> 2;

#pragma unroll
    for (int im = 0; im < 2; im++) {
        int r0 = bm + wm * 32 + im * 16 + g;
#pragma unroll
        for (int jn = 0; jn < 8; jn++) {
            int n = bn + wn * 64 + jn * 8 + 2 * m;
            float b0v = bias[n], b1v = bias[n + 1];
            float* o0 = C + (size_t)r0 * EMB + n;
            float* o1 = o0 + (size_t)8 * EMB;
            *(float2*)o0 = make_float2(acc.a[im][jn][0] + b0v, acc.a[im][jn][1] + b1v);
            *(float2*)o1 = make_float2(acc.a[im][jn][2] + b0v, acc.a[im][jn][3] + b1v);
        }
    }
}

// ---------------------------------------------------------------------------
// Flash attention v2: tf32 mma, im=2 warp tiles (32 q-rows/warp), cp.async
// double-buffered K/V staging, no cvt in the hot loop (inputs pre-rounded).
// Grid (SEQ/128, BH), 128 threads (4 warps). CTA q-tile = 128 rows.
// Smem: 2 stages x (K 64x72 + V 64x72) fp32 = 73728 B (dynamic).
// ---------------------------------------------------------------------------
#define KVS    72
#define TILE_F (64 * KVS)
#define ATT_SMEM (4 * TILE_F * 4)

__global__ void __launch_bounds__(128) attn_tc2_kernel(
    const float* __restrict__ mask,
    const float* __restrict__ attn_bias,
    const float* __restrict__ beta_p,
    const float* __restrict__ bbias_p)
{
    extern __shared__ __align__(16) float sm[];

    int qt   = blockIdx.x;
    int bh   = blockIdx.y;
    int b    = bh / NH;
    int h    = bh % NH;
    int q0   = qt * 128;
    int tid  = threadIdx.x;
    int w    = tid >> 5;
    int lane = tid & 31;
    int g    = lane >> 2;
    int m    = lane & 3;

    const float beta  = beta_p[0];
    const float bbias = bbias_p[0];
    const int masknz  = g_mask_nz;

    const float* Kg    = g_K + (size_t)bh * SEQ * HD;
    const float* Vg    = g_V + (size_t)bh * SEQ * HD;
    const float* biasg = attn_bias + (size_t)bh * SEQ;

    // ---- Q fragments (pre-rounded tf32 in g_Q): 2 x 16 rows per warp ----
    unsigned qf[2][8][4];
    {
        const float* Qb = g_Q + ((size_t)bh * SEQ + q0 + w * 32) * HD;
#pragma unroll
        for (int im = 0; im < 2; im++) {
            const float* r0 = Qb + (size_t)(im * 16 + g) * HD;
            const float* r1 = r0 + 8 * HD;
#pragma unroll
            for (int t = 0; t < 8; t++) {
                qf[im][t][0] = __float_as_uint(r0[8 * t + m]);
                qf[im][t][1] = __float_as_uint(r1[8 * t + m]);
                qf[im][t][2] = __float_as_uint(r0[8 * t + m + 4]);
                qf[im][t][3] = __float_as_uint(r1[8 * t + m + 4]);
            }
        }
    }

    float mr[2][2], lrn[2][2];
    float oa[2][8][4];
#pragma unroll
    for (int im = 0; im < 2; im++) {
        mr[im][0] = -1e30f; mr[im][1] = -1e30f;
        lrn[im][0] = 0.f;   lrn[im][1] = 0.f;
#pragma unroll
        for (int d = 0; d < 8; d++)
#pragma unroll
            for (int i = 0; i < 4; i++) oa[im][d][i] = 0.f;
    }

    unsigned sbase = (unsigned)__cvta_generic_to_shared(sm);
    int lrow = tid >> 4;   // 0..7
    int cir  = tid & 15;   // 16B chunk within row

    auto issue_tile = [&](int kt) {
        unsigned kst = sbase + (unsigned)(kt & 1) * (2 * TILE_F * 4);
        unsigned vst = kst + TILE_F * 4;
        const float* kp = Kg + (size_t)(kt * 64) * HD;
        const float* vp = Vg + (size_t)(kt * 64) * HD;
#pragma unroll
        for (int u = 0; u < 8; u++) {
            int row = u * 8 + lrow;
            unsigned soff = (unsigned)(row * KVS + cir * 4) * 4;
            cp_async16(kst + soff, kp + (size_t)row * HD + cir * 4);
            cp_async16(vst + soff, vp + (size_t)row * HD + cir * 4);
        }
        cp_commit();
    };

    issue_tile(0);

    const int NT = SEQ / 64;
    for (int kt = 0; kt < NT; kt++) {
        if (kt + 1 < NT) { issue_tile(kt + 1); cp_wait<1>(); }
        else             { cp_wait<0>(); }
        __syncthreads();

        const float* Ksb = sm + (kt & 1) * 2 * TILE_F;
        const float* Vsb = Ksb + TILE_F;
        int k0 = kt * 64;

        // ---- Scores ----
        float sc[2][8][4];
#pragma unroll
        for (int im = 0; im < 2; im++)
#pragma unroll
            for (int j = 0; j < 8; j++)
#pragma unroll
                for (int i = 0; i < 4; i++) sc[im][j][i] = 0.f;

#pragma unroll
        for (int t = 0; t < 8; t++) {
#pragma unroll
            for (int j = 0; j < 8; j++) {
                const float* kr = Ksb + (8 * j + g) * KVS + 8 * t + m;
                unsigned b0 = __float_as_uint(kr[0]);
                unsigned b1 = __float_as_uint(kr[4]);
                mma_tf32(sc[0][j], qf[0][t], b0, b1);
                mma_tf32(sc[1][j], qf[1][t], b0, b1);
            }
        }

        // ---- bias (+mask) ----
#pragma unroll
        for (int j = 0; j < 8; j++) {
            float2 bv = *(const float2*)(biasg + k0 + 8 * j + 2 * m);
            float b0v = beta * bv.x + bbias;
            float b1v = beta * bv.y + bbias;
#pragma unroll
            for (int im = 0; im < 2; im++) {
                sc[im][j][0] += b0v; sc[im][j][1] += b1v;
                sc[im][j][2] += b0v; sc[im][j][3] += b1v;
                if (masknz) {
                    int qr = q0 + w * 32 + im * 16 + g;
                    const float* m0p = mask + ((size_t)b * SEQ + qr) * SEQ + k0 + 8 * j + 2 * m;
                    const float* m1p = m0p + (size_t)8 * SEQ;
                    sc[im][j][0] += m0p[0]; sc[im][j][1] += m0p[1];
                    sc[im][j][2] += m1p[0]; sc[im][j][3] += m1p[1];
                }
            }
        }

        // ---- Online softmax per im ----
#pragma unroll
        for (int im = 0; im < 2; im++) {
            float mx0 = sc[im][0][0], mx1 = sc[im][0][2];
#pragma unroll
            for (int j = 0; j < 8; j++) {
                mx0 = fmaxf(mx0, fmaxf(sc[im][j][0], sc[im][j][1]));
                mx1 = fmaxf(mx1, fmaxf(sc[im][j][2], sc[im][j][3]));
            }
            mx0 = fmaxf(mx0, __shfl_xor_sync(0xffffffffu, mx0, 1));
            mx0 = fmaxf(mx0, __shfl_xor_sync(0xffffffffu, mx0, 2));
            mx1 = fmaxf(mx1, __shfl_xor_sync(0xffffffffu, mx1, 1));
            mx1 = fmaxf(mx1, __shfl_xor_sync(0xffffffffu, mx1, 2));

            float mn0 = fmaxf(mr[im][0], mx0);
            float mn1 = fmaxf(mr[im][1], mx1);
            float al0 = __expf(mr[im][0] - mn0);
            float al1 = __expf(mr[im][1] - mn1);

            float s0 = 0.f, s1 = 0.f;
#pragma unroll
            for (int j = 0; j < 8; j++) {
                sc[im][j][0] = __expf(sc[im][j][0] - mn0);
                sc[im][j][1] = __expf(sc[im][j][1] - mn0);
                sc[im][j][2] = __expf(sc[im][j][2] - mn1);
                sc[im][j][3] = __expf(sc[im][j][3] - mn1);
                s0 += sc[im][j][0] + sc[im][j][1];
                s1 += sc[im][j][2] + sc[im][j][3];
            }
            s0 += __shfl_xor_sync(0xffffffffu, s0, 1);
            s0 += __shfl_xor_sync(0xffffffffu, s0, 2);
            s1 += __shfl_xor_sync(0xffffffffu, s1, 1);
            s1 += __shfl_xor_sync(0xffffffffu, s1, 2);

            lrn[im][0] = lrn[im][0] * al0 + s0;
            lrn[im][1] = lrn[im][1] * al1 + s1;
            mr[im][0] = mn0; mr[im][1] = mn1;
#pragma unroll
            for (int d = 0; d < 8; d++) {
                oa[im][d][0] *= al0; oa[im][d][1] *= al0;
                oa[im][d][2] *= al1; oa[im][d][3] *= al1;
            }
        }

        // ---- PV: P C->A layout conversion + mma, V frags shared over im ----
        int src0 = (lane & ~3) | (m >> 1);
        int src1 = src0 + 2;
        int sel  = m & 1;
#pragma unroll
        for (int j = 0; j < 8; j++) {
            unsigned pa[2][4];
#pragma unroll
            for (int im = 0; im < 2; im++) {
                unsigned p0 = cvt_tf32(sc[im][j][0]);
                unsigned p1 = cvt_tf32(sc[im][j][1]);
                unsigned p2 = cvt_tf32(sc[im][j][2]);
                unsigned p3 = cvt_tf32(sc[im][j][3]);
                unsigned x0 = __shfl_sync(0xffffffffu, p0, src0);
                unsigned x1 = __shfl_sync(0xffffffffu, p1, src0);
                pa[im][0] = sel ? x1 : x0;
                unsigned x2 = __shfl_sync(0xffffffffu, p2, src0);
                unsigned x3 = __shfl_sync(0xffffffffu, p3, src0);
                pa[im][1] = sel ? x3 : x2;
                unsigned y0 = __shfl_sync(0xffffffffu, p0, src1);
                unsigned y1 = __shfl_sync(0xffffffffu, p1, src1);
                pa[im][2] = sel ? y1 : y0;
                unsigned y2 = __shfl_sync(0xffffffffu, p2, src1);
                unsigned y3 = __shfl_sync(0xffffffffu, p3, src1);
                pa[im][3] = sel ? y3 : y2;
            }
#pragma unroll
            for (int d = 0; d < 8; d++) {
                const float* vr = Vsb + (8 * j + m) * KVS + 8 * d + g;
                unsigned b0 = __float_as_uint(vr[0]);
                unsigned b1 = __float_as_uint(vr[4 * KVS]);
                mma_tf32(oa[0][d], pa[0], b0, b1);
                mma_tf32(oa[1][d], pa[1], b0, b1);
            }
        }
        __syncthreads();
    }

    // ---- Epilogue ----
#pragma unroll
    for (int im = 0; im < 2; im++) {
        float inv0 = 1.f / lrn[im][0];
        float inv1 = 1.f / lrn[im][1];
        int qr = q0 + w * 32 + im * 16 + g;
        float* O0 = g_O + ((size_t)(b * SEQ + qr)) * EMB + h * HD;
        float* O1 = O0 + (size_t)8 * EMB;
#pragma unroll
        for (int d = 0; d < 8; d++) {
            int c = 8 * d + 2 * m;
            *(float2*)(O0 + c) = make_float2(oa[im][d][0] * inv0, oa[im][d][1] * inv0);
            *(float2*)(O1 + c) = make_float2(oa[im][d][2] * inv1, oa[im][d][3] * inv1);
        }
    }
}

// ---------------------------------------------------------------------------
// Launch
// ---------------------------------------------------------------------------
extern "C" void kernel_launch(void* const* d_in, const int* in_sizes, int n_in,
                              void* d_out, int out_size) {
    const float* X     = (const float*)d_in[0];
    const float* mask  = (const float*)d_in[1];
    const float* abias = (const float*)d_in[2];
    const float* Wq    = (const float*)d_in[3];
    const float* bq    = (const float*)d_in[4];
    const float* Wk    = (const float*)d_in[5];
    const float* bk    = (const float*)d_in[6];
    const float* Wv    = (const float*)d_in[7];
    const float* bv    = (const float*)d_in[8];
    const float* Wo    = (const float*)d_in[9];
    const float* bo    = (const float*)d_in[10];
    const float* beta  = (const float*)d_in[11];
    const float* bbias = (const float*)d_in[12];
    float* out = (float*)d_out;

    cudaFuncSetAttribute(attn_tc2_kernel,
                         cudaFuncAttributeMaxDynamicSharedMemorySize, ATT_SMEM);

    reset_flag_kernel<<<1, 32>>>();
    scan_mask_kernel<<<1024, 256>>>(mask, BSZ * SEQ * SEQ / 4);
    qkv_gemm_tc_kernel<<<dim3(18, 32), 256>>>(X, Wq, bq, Wk, bk, Wv, bv);
    attn_tc2_kernel<<<dim3(SEQ / 128, BH), 128, ATT_SMEM>>>(mask, abias, beta, bbias);
    oproj_gemm_tc_kernel<<<dim3(6, 32), 256>>>(Wo, bo, out);
}